// round 9
// baseline (speedup 1.0000x reference)
#include <cuda_runtime.h>
#include <cstdint>

#define BATCH 8192
#define HID   512
#define HID2  1024
#define NSTEPS 10
#define NEVAL  (NSTEPS*4)

// ---------------- scratch (device globals; no allocation anywhere) -----------
__device__ float g_x1[(size_t)BATCH * HID2];    // tanh out, tf32-rounded
__device__ float g_x2[(size_t)BATCH * HID2];
__device__ float g_acc[(size_t)BATCH * HID];    // fp32 RK4 accumulator
__device__ float g_htmp[(size_t)BATCH * HID];   // tf32-rounded stage input
__device__ float g_h[(size_t)BATCH * HID];      // fp32 state
__device__ float g_hr[(size_t)BATCH * HID];     // tf32-rounded copy of h
__device__ float g_w1[(size_t)HID2 * HID];      // tf32-rounded weights
__device__ float g_w2[(size_t)HID2 * HID2];
__device__ float g_w3[(size_t)HID  * HID2];
__device__ float g_c1[NEVAL * HID2];

// ---------------- helpers ----------------------------------------------------
__device__ __forceinline__ float to_tf32(float x) {
    float y;
    asm("cvt.rna.tf32.f32 %0, %1;" : "=f"(y) : "f"(x));
    return y;
}

__device__ __forceinline__ void mma8(float* d, const float* a, const float* b) {
    const unsigned* A = (const unsigned*)a;
    const unsigned* B = (const unsigned*)b;
    asm volatile(
        "mma.sync.aligned.m16n8k8.row.col.f32.tf32.tf32.f32 "
        "{%0,%1,%2,%3}, {%4,%5,%6,%7}, {%8,%9}, {%0,%1,%2,%3};\n"
        : "+f"(d[0]), "+f"(d[1]), "+f"(d[2]), "+f"(d[3])
        : "r"(A[0]), "r"(A[1]), "r"(A[2]), "r"(A[3]), "r"(B[0]), "r"(B[1]));
}

// ---------------- prep kernels -----------------------------------------------
__global__ void round4_kernel(const float4* __restrict__ src, float4* __restrict__ dst, int n4) {
    int i = blockIdx.x * blockDim.x + threadIdx.x;
    if (i < n4) {
        float4 v = src[i];
        dst[i] = make_float4(to_tf32(v.x), to_tf32(v.y), to_tf32(v.z), to_tf32(v.w));
    }
}

// c1[e][j] = b1[j] + sum_i W1[j,i]*(t_e*Wt[i]+bt[i])
__global__ void c1_all_kernel(const float* __restrict__ W1, const float* __restrict__ b1,
                              const float* __restrict__ Wt, const float* __restrict__ bt,
                              float dt, float* __restrict__ out) {
    int gw = (blockIdx.x * blockDim.x + threadIdx.x) >> 5;
    int lane = threadIdx.x & 31;
    int e = gw >> 10;
    int j = gw & 1023;
    if (e >= NEVAL) return;
    int step = e >> 2, st = e & 3;
    float tv = step * dt + ((st == 0) ? 0.0f : (st == 3) ? dt : 0.5f * dt);
    const float* row = W1 + (size_t)j * HID;
    float s = 0.0f;
    #pragma unroll 4
    for (int i = lane; i < HID; i += 32)
        s = fmaf(row[i], fmaf(tv, Wt[i], bt[i]), s);
    #pragma unroll
    for (int o = 16; o; o >>= 1) s += __shfl_xor_sync(0xffffffffu, s, o);
    if (lane == 0) out[e * HID2 + j] = b1[j] + s;
}

// ---------------- GEMM: C = act( A[M,K] @ Bw[N,K]^T + bias[N] ) --------------
// CTA tile 128x128, 128 threads = 4 warps in a 2x2 grid, warp tile 64x64.
// occ 2 (two independent CTAs/SM hide each other's barriers), crossbar traffic
// 64 KB/CTA/chunk -> 1024 cyc/SM vs tensor 2048 cyc/SM: tensor-bound.
// cp.async 3-stage pipeline + PDL. R2-style scalar LDS scheduling.
// stage < 0 : tanh epilogue -> C (tf32). stage 0..3: fused RK4 (N == HID).
__global__ __launch_bounds__(128, 2)
void gemm_kernel(const float* __restrict__ A, const float* __restrict__ Bw,
                 const float* __restrict__ bias, float* __restrict__ C,
                 int N, int K, int stage, float dt,
                 float* __restrict__ hbuf, float* __restrict__ accbuf,
                 float* __restrict__ htmp, float* __restrict__ hr) {
    extern __shared__ float smem[];
    const int LDT = 36;                 // padded stride (floats)
    const int STG_F = 128 * LDT;        // floats per stage per matrix
    float* As = smem;                   // 3 A stages
    float* Bs = smem + 3 * STG_F;       // 3 B stages

    const int t = threadIdx.x;
    const int warp = t >> 5, lane = t & 31;
    const int wm = warp & 1, wn = warp >> 1;  // 2 x 2 warp grid, warp tile 64x64
    const int g = lane >> 2, q = lane & 3;
    const int bm = blockIdx.y * 128;
    const int bn = blockIdx.x * 128;

    const int c4  = (t & 7) * 4;        // k-offset (floats) this thread copies
    const int r0l = t >> 3;             // first row this thread copies (0..15)

    const float* Ag = A  + (size_t)(bm + r0l) * K + c4;
    const float* Bg = Bw + (size_t)(bn + r0l) * K + c4;

    unsigned sA0 = (unsigned)__cvta_generic_to_shared(As + r0l * LDT + c4);
    unsigned sB0 = (unsigned)__cvta_generic_to_shared(Bs + r0l * LDT + c4);

    float acc[4][8][4];
    #pragma unroll
    for (int i = 0; i < 4; i++)
        #pragma unroll
        for (int j = 0; j < 8; j++)
            #pragma unroll
            for (int v = 0; v < 4; v++) acc[i][j][v] = 0.0f;

    const int KT = K >> 5;

    #define LOAD_A(kt, s)                                                            \
    {                                                                                \
        const float* ap = Ag + (kt) * 32;                                            \
        unsigned sa = sA0 + (unsigned)(s) * (STG_F * 4);                             \
        _Pragma("unroll")                                                            \
        for (int i = 0; i < 8; i++)                                                  \
            asm volatile("cp.async.cg.shared.global [%0], [%1], 16;\n"               \
                         :: "r"(sa + i * 16 * LDT * 4), "l"(ap + (size_t)i * 16 * K)); \
    }
    #define LOAD_B(kt, s)                                                            \
    {                                                                                \
        const float* bp = Bg + (kt) * 32;                                            \
        unsigned sb = sB0 + (unsigned)(s) * (STG_F * 4);                             \
        _Pragma("unroll")                                                            \
        for (int i = 0; i < 8; i++)                                                  \
            asm volatile("cp.async.cg.shared.global [%0], [%1], 16;\n"               \
                         :: "r"(sb + i * 16 * LDT * 4), "l"(bp + (size_t)i * 16 * K)); \
    }
    #define COMMIT() asm volatile("cp.async.commit_group;\n")

    // --- prologue: weights first (independent of predecessor), then gate on A ---
    LOAD_B(0, 0);
    LOAD_B(1, 1);
    COMMIT();                                       // group: B0+B1
    asm volatile("griddepcontrol.wait;" ::: "memory");
    LOAD_A(0, 0);
    COMMIT();                                       // group: A0
    LOAD_A(1, 1);
    COMMIT();                                       // group: A1
    asm volatile("griddepcontrol.launch_dependents;" ::: "memory");

    for (int kt = 0; kt < KT; kt++) {
        asm volatile("cp.async.wait_group 1;\n");
        __syncthreads();
        const int cur = kt % 3;
        const float* Asb = As + cur * STG_F;
        const float* Bsb = Bs + cur * STG_F;
        #pragma unroll
        for (int s = 0; s < 4; s++) {
            float bf[8][2];
            #pragma unroll
            for (int fn = 0; fn < 8; fn++) {
                int c0 = wn * 64 + fn * 8 + g;
                bf[fn][0] = Bsb[c0 * LDT + s * 8 + q];
                bf[fn][1] = Bsb[c0 * LDT + s * 8 + q + 4];
            }
            #pragma unroll
            for (int fm = 0; fm < 4; fm++) {
                int r0 = wm * 64 + fm * 16 + g;
                float af[4];
                af[0] = Asb[r0 * LDT + s * 8 + q];
                af[1] = Asb[(r0 + 8) * LDT + s * 8 + q];
                af[2] = Asb[r0 * LDT + s * 8 + q + 4];
                af[3] = Asb[(r0 + 8) * LDT + s * 8 + q + 4];
                #pragma unroll
                for (int fn = 0; fn < 8; fn++)
                    mma8(acc[fm][fn], af, bf[fn]);
            }
        }
        if (kt + 2 < KT) {
            const int nxt = (kt + 2) % 3;
            LOAD_A(kt + 2, nxt);
            LOAD_B(kt + 2, nxt);
            COMMIT();
        }
    }
    #undef LOAD_A
    #undef LOAD_B
    #undef COMMIT

    // ---------------- epilogue ----------------
    #pragma unroll
    for (int fm = 0; fm < 4; fm++) {
        int r0 = bm + wm * 64 + fm * 16 + g;
        int r1 = r0 + 8;
        #pragma unroll
        for (int fn = 0; fn < 8; fn++) {
            int c = bn + wn * 64 + fn * 8 + 2 * q;
            float bc0 = bias[c], bc1 = bias[c + 1];
            float v[4];
            v[0] = acc[fm][fn][0] + bc0;
            v[1] = acc[fm][fn][1] + bc1;
            v[2] = acc[fm][fn][2] + bc0;
            v[3] = acc[fm][fn][3] + bc1;
            int idx[4] = { r0 * N + c, r0 * N + c + 1, r1 * N + c, r1 * N + c + 1 };
            if (stage < 0) {
                #pragma unroll
                for (int u = 0; u < 4; u++)
                    C[idx[u]] = to_tf32(tanhf(v[u]));
            } else if (stage == 0) {
                #pragma unroll
                for (int u = 0; u < 4; u++) {
                    accbuf[idx[u]] = v[u];
                    htmp[idx[u]]   = to_tf32(hbuf[idx[u]] + 0.5f * dt * v[u]);
                }
            } else if (stage == 1) {
                #pragma unroll
                for (int u = 0; u < 4; u++) {
                    accbuf[idx[u]] += 2.0f * v[u];
                    htmp[idx[u]]    = to_tf32(hbuf[idx[u]] + 0.5f * dt * v[u]);
                }
            } else if (stage == 2) {
                #pragma unroll
                for (int u = 0; u < 4; u++) {
                    accbuf[idx[u]] += 2.0f * v[u];
                    htmp[idx[u]]    = to_tf32(hbuf[idx[u]] + dt * v[u]);
                }
            } else {
                #pragma unroll
                for (int u = 0; u < 4; u++) {
                    float hn = hbuf[idx[u]] + (dt / 6.0f) * (accbuf[idx[u]] + v[u]);
                    hbuf[idx[u]] = hn;
                    hr[idx[u]]   = to_tf32(hn);
                }
            }
        }
    }
}

// ---------------- launch -----------------------------------------------------
static void launch_gemm(dim3 grd, dim3 blk, int smem,
                        const float* A, const float* Bw, const float* bias, float* C,
                        int N, int K, int stage, float dt,
                        float* hbuf, float* accbuf, float* htmp, float* hr) {
    cudaLaunchConfig_t cfg = {};
    cfg.gridDim = grd;
    cfg.blockDim = blk;
    cfg.dynamicSmemBytes = (size_t)smem;
    cfg.stream = 0;
    cudaLaunchAttribute at[1];
    at[0].id = cudaLaunchAttributeProgrammaticStreamSerialization;
    at[0].val.programmaticStreamSerializationAllowed = 1;
    cfg.attrs = at;
    cfg.numAttrs = 1;
    cudaLaunchKernelEx(&cfg, gemm_kernel, A, Bw, bias, C, N, K, stage, dt,
                       hbuf, accbuf, htmp, hr);
}

extern "C" void kernel_launch(void* const* d_in, const int* in_sizes, int n_in,
                              void* d_out, int out_size) {
    const float* h  = (const float*)d_in[0];
    const float* W1 = (const float*)d_in[1];
    const float* b1 = (const float*)d_in[2];
    const float* W2 = (const float*)d_in[3];
    const float* b2 = (const float*)d_in[4];
    const float* W3 = (const float*)d_in[5];
    const float* b3 = (const float*)d_in[6];
    const float* Wt = (const float*)d_in[7];
    const float* bt = (const float*)d_in[8];
    (void)in_sizes; (void)n_in; (void)out_size;

    float *x1, *x2, *accb, *htmp, *hbuf, *hr, *w1, *w2, *w3, *c1;
    cudaGetSymbolAddress((void**)&x1,   g_x1);
    cudaGetSymbolAddress((void**)&x2,   g_x2);
    cudaGetSymbolAddress((void**)&accb, g_acc);
    cudaGetSymbolAddress((void**)&htmp, g_htmp);
    cudaGetSymbolAddress((void**)&hbuf, g_h);
    cudaGetSymbolAddress((void**)&hr,   g_hr);
    cudaGetSymbolAddress((void**)&w1,   g_w1);
    cudaGetSymbolAddress((void**)&w2,   g_w2);
    cudaGetSymbolAddress((void**)&w3,   g_w3);
    cudaGetSymbolAddress((void**)&c1,   g_c1);

    const int SMEM = 2 * 3 * 128 * 36 * (int)sizeof(float);  // 110592 B
    cudaFuncSetAttribute(gemm_kernel, cudaFuncAttributeMaxDynamicSharedMemorySize, SMEM);

    cudaMemcpyAsync(hbuf, h, (size_t)BATCH * HID * sizeof(float), cudaMemcpyDeviceToDevice);

    const float dt = 1.0f / NSTEPS;

    // prep: tf32-round weights and h, compute all 40 c1 vectors
    {
        int n4;
        n4 = HID2 * HID / 4;   round4_kernel<<<(n4 + 255) / 256, 256>>>((const float4*)W1, (float4*)w1, n4);
        n4 = HID2 * HID2 / 4;  round4_kernel<<<(n4 + 255) / 256, 256>>>((const float4*)W2, (float4*)w2, n4);
        n4 = HID * HID2 / 4;   round4_kernel<<<(n4 + 255) / 256, 256>>>((const float4*)W3, (float4*)w3, n4);
        n4 = BATCH * HID / 4;  round4_kernel<<<(n4 + 255) / 256, 256>>>((const float4*)h,  (float4*)hr, n4);
        c1_all_kernel<<<NEVAL * HID2 / 8, 256>>>(W1, b1, Wt, bt, dt, c1);
    }

    dim3 blk(128);
    dim3 grd1(HID2 / 128, BATCH / 128);    // 8 x 64 = 512 CTAs
    dim3 grd3(HID  / 128, BATCH / 128);    // 4 x 64 = 256 CTAs

    for (int s = 0; s < NSTEPS; s++) {
        for (int st = 0; st < 4; st++) {
            const float* Ain = (st == 0) ? hr : htmp;
            const float* c1e = c1 + (s * 4 + st) * HID2;
            launch_gemm(grd1, blk, SMEM, Ain, w1, c1e, x1, HID2, HID, -1, dt,
                        nullptr, nullptr, nullptr, nullptr);
            launch_gemm(grd1, blk, SMEM, x1, w2, b2, x2, HID2, HID2, -1, dt,
                        nullptr, nullptr, nullptr, nullptr);
            launch_gemm(grd3, blk, SMEM, x2, w3, b3, nullptr, HID, HID2, st, dt,
                        hbuf, accb, htmp, hr);
        }
    }

    cudaMemcpyAsync(d_out, hbuf, (size_t)BATCH * HID * sizeof(float), cudaMemcpyDeviceToDevice);
}

// round 11
// speedup vs baseline: 1.5184x; 1.5184x over previous
#include <cuda_runtime.h>
#include <cuda_fp16.h>
#include <cstdint>

#define BATCH 8192
#define HID   512
#define HID2  1024
#define NSTEPS 10
#define NEVAL  (NSTEPS*4)

// ---------------- scratch (device globals; no allocation anywhere) -----------
__device__ __half g_x1[(size_t)BATCH * HID2];    // tanh out, fp16
__device__ __half g_x2[(size_t)BATCH * HID2];
__device__ float  g_acc[(size_t)BATCH * HID];    // fp32 RK4 accumulator
__device__ __half g_htmp[(size_t)BATCH * HID];   // fp16 stage input
__device__ float  g_h[(size_t)BATCH * HID];      // fp32 state
__device__ __half g_hr[(size_t)BATCH * HID];     // fp16 copy of h
__device__ __half g_w1[(size_t)HID2 * HID];      // fp16 weights
__device__ __half g_w2[(size_t)HID2 * HID2];
__device__ __half g_w3[(size_t)HID  * HID2];
__device__ float  g_c1[NEVAL * HID2];            // fp32

// ---------------- helpers ----------------------------------------------------
__device__ __forceinline__ void mma16(float* d, const unsigned* a, const unsigned* b) {
    asm volatile(
        "mma.sync.aligned.m16n8k16.row.col.f32.f16.f16.f32 "
        "{%0,%1,%2,%3}, {%4,%5,%6,%7}, {%8,%9}, {%0,%1,%2,%3};\n"
        : "+f"(d[0]), "+f"(d[1]), "+f"(d[2]), "+f"(d[3])
        : "r"(a[0]), "r"(a[1]), "r"(a[2]), "r"(a[3]), "r"(b[0]), "r"(b[1]));
}

// ---------------- prep kernels -----------------------------------------------
// fp32 -> fp16 (rne), 2 elems/thread
__global__ void half2_kernel(const float2* __restrict__ src, __half2* __restrict__ dst, int n2) {
    int i = blockIdx.x * blockDim.x + threadIdx.x;
    if (i < n2) {
        float2 v = src[i];
        dst[i] = __floats2half2_rn(v.x, v.y);
    }
}

// c1[e][j] = b1[j] + sum_i W1[j,i]*(t_e*Wt[i]+bt[i])   (fp32 inputs)
__global__ void c1_all_kernel(const float* __restrict__ W1, const float* __restrict__ b1,
                              const float* __restrict__ Wt, const float* __restrict__ bt,
                              float dt, float* __restrict__ out) {
    int gw = (blockIdx.x * blockDim.x + threadIdx.x) >> 5;
    int lane = threadIdx.x & 31;
    int e = gw >> 10;
    int j = gw & 1023;
    if (e >= NEVAL) return;
    int step = e >> 2, st = e & 3;
    float tv = step * dt + ((st == 0) ? 0.0f : (st == 3) ? dt : 0.5f * dt);
    const float* row = W1 + (size_t)j * HID;
    float s = 0.0f;
    #pragma unroll 4
    for (int i = lane; i < HID; i += 32)
        s = fmaf(row[i], fmaf(tv, Wt[i], bt[i]), s);
    #pragma unroll
    for (int o = 16; o; o >>= 1) s += __shfl_xor_sync(0xffffffffu, s, o);
    if (lane == 0) out[e * HID2 + j] = b1[j] + s;
}

// ---------------- GEMM: C = act( A[M,K] @ Bw[N,K]^T + bias[N] ) --------------
// fp16 operands (same 11-bit mantissa as tf32), fp32 accumulate.
// CTA 128x128, 256 thr, 2(M)x4(N) warps, warp tile 64x32. m16n8k16 HMMA:
// 32 mma + 48 LDS.32 per warp per 32-k chunk (half of the tf32 counts).
// 3-stage cp.async + PDL, occ 2.
// stage < 0 : tanh epilogue -> C (fp16). stage 0..3: fused RK4 (N == HID).
__global__ __launch_bounds__(256, 2)
void gemm_kernel(const __half* __restrict__ A, const __half* __restrict__ Bw,
                 const float* __restrict__ bias, __half* __restrict__ C,
                 int N, int K, int stage, float dt,
                 float* __restrict__ hbuf, float* __restrict__ accbuf,
                 __half* __restrict__ htmp, __half* __restrict__ hr) {
    extern __shared__ __half smem[];
    const int LDTW  = 20;               // padded row stride in 32-bit words (40 halfs, 80 B)
    const int STG_B = 128 * 80;         // bytes per stage per matrix (10240)
    __half* As = smem;                  // 3 A stages
    __half* Bs = smem + 3 * (STG_B / 2);

    const int t = threadIdx.x;
    const int warp = t >> 5, lane = t & 31;
    const int wm = warp & 1, wn = warp >> 1;  // 2 x 4 warp grid, warp tile 64x32
    const int g = lane >> 2, q = lane & 3;
    const int bm = blockIdx.y * 128;
    const int bn = blockIdx.x * 128;

    // copy mapping: thread covers rows {t>>2, t>>2 + 64}, 16B segment (t&3)
    const int row0 = t >> 2;
    const int seg  = t & 3;

    const __half* Ag = A  + (size_t)(bm + row0) * K + seg * 8;
    const __half* Bg = Bw + (size_t)(bn + row0) * K + seg * 8;

    unsigned sA0 = (unsigned)__cvta_generic_to_shared(As) + row0 * 80 + seg * 16;
    unsigned sB0 = (unsigned)__cvta_generic_to_shared(Bs) + row0 * 80 + seg * 16;

    float acc[4][4][4];
    #pragma unroll
    for (int i = 0; i < 4; i++)
        #pragma unroll
        for (int j = 0; j < 4; j++)
            #pragma unroll
            for (int v = 0; v < 4; v++) acc[i][j][v] = 0.0f;

    const int KT = K >> 5;

    #define LOAD_A(kt, s)                                                              \
    {                                                                                  \
        const __half* ap = Ag + (kt) * 32;                                             \
        unsigned sa = sA0 + (unsigned)(s) * STG_B;                                     \
        _Pragma("unroll")                                                              \
        for (int i = 0; i < 2; i++)                                                    \
            asm volatile("cp.async.cg.shared.global [%0], [%1], 16;\n"                 \
                         :: "r"(sa + i * 64 * 80), "l"(ap + (size_t)i * 64 * K));      \
    }
    #define LOAD_B(kt, s)                                                              \
    {                                                                                  \
        const __half* bp = Bg + (kt) * 32;                                             \
        unsigned sb = sB0 + (unsigned)(s) * STG_B;                                     \
        _Pragma("unroll")                                                              \
        for (int i = 0; i < 2; i++)                                                    \
            asm volatile("cp.async.cg.shared.global [%0], [%1], 16;\n"                 \
                         :: "r"(sb + i * 64 * 80), "l"(bp + (size_t)i * 64 * K));      \
    }
    #define COMMIT() asm volatile("cp.async.commit_group;\n")

    // --- prologue: weights first (independent of predecessor), then gate on A ---
    LOAD_B(0, 0);
    LOAD_B(1, 1);
    COMMIT();                                       // group: B0+B1
    asm volatile("griddepcontrol.wait;" ::: "memory");
    LOAD_A(0, 0);
    COMMIT();                                       // group: A0
    LOAD_A(1, 1);
    COMMIT();                                       // group: A1
    asm volatile("griddepcontrol.launch_dependents;" ::: "memory");

    for (int kt = 0; kt < KT; kt++) {
        asm volatile("cp.async.wait_group 1;\n");
        __syncthreads();
        const int cur = kt % 3;
        const unsigned* Asw = (const unsigned*)(As + cur * (STG_B / 2));
        const unsigned* Bsw = (const unsigned*)(Bs + cur * (STG_B / 2));
        #pragma unroll
        for (int s = 0; s < 2; s++) {              // two k16 steps per 32-chunk
            const int w0 = s * 8 + q;              // b32 word (halfs 16s+2q, +1)
            float af_dummy;
            (void)af_dummy;
            unsigned bf[4][2];
            #pragma unroll
            for (int fn = 0; fn < 4; fn++) {
                int c0 = wn * 32 + fn * 8 + g;
                bf[fn][0] = Bsw[c0 * LDTW + w0];
                bf[fn][1] = Bsw[c0 * LDTW + w0 + 4];
            }
            #pragma unroll
            for (int fm = 0; fm < 4; fm++) {
                int r0 = wm * 64 + fm * 16 + g;
                unsigned af[4];
                af[0] = Asw[r0 * LDTW + w0];
                af[1] = Asw[(r0 + 8) * LDTW + w0];
                af[2] = Asw[r0 * LDTW + w0 + 4];
                af[3] = Asw[(r0 + 8) * LDTW + w0 + 4];
                #pragma unroll
                for (int fn = 0; fn < 4; fn++)
                    mma16(acc[fm][fn], af, bf[fn]);
            }
        }
        if (kt + 2 < KT) {
            const int nxt = (kt + 2) % 3;
            LOAD_A(kt + 2, nxt);
            LOAD_B(kt + 2, nxt);
            COMMIT();
        }
    }
    #undef LOAD_A
    #undef LOAD_B
    #undef COMMIT

    // ---------------- epilogue ----------------
    #pragma unroll
    for (int fm = 0; fm < 4; fm++) {
        int r0 = bm + wm * 64 + fm * 16 + g;
        int r1 = r0 + 8;
        #pragma unroll
        for (int fn = 0; fn < 4; fn++) {
            int c = bn + wn * 32 + fn * 8 + 2 * q;
            float bc0 = bias[c], bc1 = bias[c + 1];
            float v[4];
            v[0] = acc[fm][fn][0] + bc0;
            v[1] = acc[fm][fn][1] + bc1;
            v[2] = acc[fm][fn][2] + bc0;
            v[3] = acc[fm][fn][3] + bc1;
            int idx[4] = { r0 * N + c, r0 * N + c + 1, r1 * N + c, r1 * N + c + 1 };
            if (stage < 0) {
                #pragma unroll
                for (int u = 0; u < 4; u++)
                    C[idx[u]] = __float2half_rn(tanhf(v[u]));
            } else if (stage == 0) {
                #pragma unroll
                for (int u = 0; u < 4; u++) {
                    accbuf[idx[u]] = v[u];
                    htmp[idx[u]]   = __float2half_rn(hbuf[idx[u]] + 0.5f * dt * v[u]);
                }
            } else if (stage == 1) {
                #pragma unroll
                for (int u = 0; u < 4; u++) {
                    accbuf[idx[u]] += 2.0f * v[u];
                    htmp[idx[u]]    = __float2half_rn(hbuf[idx[u]] + 0.5f * dt * v[u]);
                }
            } else if (stage == 2) {
                #pragma unroll
                for (int u = 0; u < 4; u++) {
                    accbuf[idx[u]] += 2.0f * v[u];
                    htmp[idx[u]]    = __float2half_rn(hbuf[idx[u]] + dt * v[u]);
                }
            } else {
                #pragma unroll
                for (int u = 0; u < 4; u++) {
                    float hn = hbuf[idx[u]] + (dt / 6.0f) * (accbuf[idx[u]] + v[u]);
                    hbuf[idx[u]] = hn;
                    hr[idx[u]]   = __float2half_rn(hn);
                }
            }
        }
    }
}

// ---------------- launch -----------------------------------------------------
static void launch_gemm(dim3 grd, dim3 blk, int smem,
                        const __half* A, const __half* Bw, const float* bias, __half* C,
                        int N, int K, int stage, float dt,
                        float* hbuf, float* accbuf, __half* htmp, __half* hr) {
    cudaLaunchConfig_t cfg = {};
    cfg.gridDim = grd;
    cfg.blockDim = blk;
    cfg.dynamicSmemBytes = (size_t)smem;
    cfg.stream = 0;
    cudaLaunchAttribute at[1];
    at[0].id = cudaLaunchAttributeProgrammaticStreamSerialization;
    at[0].val.programmaticStreamSerializationAllowed = 1;
    cfg.attrs = at;
    cfg.numAttrs = 1;
    cudaLaunchKernelEx(&cfg, gemm_kernel, A, Bw, bias, C, N, K, stage, dt,
                       hbuf, accbuf, htmp, hr);
}

extern "C" void kernel_launch(void* const* d_in, const int* in_sizes, int n_in,
                              void* d_out, int out_size) {
    const float* h  = (const float*)d_in[0];
    const float* W1 = (const float*)d_in[1];
    const float* b1 = (const float*)d_in[2];
    const float* W2 = (const float*)d_in[3];
    const float* b2 = (const float*)d_in[4];
    const float* W3 = (const float*)d_in[5];
    const float* b3 = (const float*)d_in[6];
    const float* Wt = (const float*)d_in[7];
    const float* bt = (const float*)d_in[8];
    (void)in_sizes; (void)n_in; (void)out_size;

    __half *x1, *x2, *htmp, *hr, *w1, *w2, *w3;
    float *accb, *hbuf, *c1;
    cudaGetSymbolAddress((void**)&x1,   g_x1);
    cudaGetSymbolAddress((void**)&x2,   g_x2);
    cudaGetSymbolAddress((void**)&accb, g_acc);
    cudaGetSymbolAddress((void**)&htmp, g_htmp);
    cudaGetSymbolAddress((void**)&hbuf, g_h);
    cudaGetSymbolAddress((void**)&hr,   g_hr);
    cudaGetSymbolAddress((void**)&w1,   g_w1);
    cudaGetSymbolAddress((void**)&w2,   g_w2);
    cudaGetSymbolAddress((void**)&w3,   g_w3);
    cudaGetSymbolAddress((void**)&c1,   g_c1);

    const int SMEM = 6 * 128 * 80;      // 61440 B (3 stages x (A+B))
    cudaFuncSetAttribute(gemm_kernel, cudaFuncAttributeMaxDynamicSharedMemorySize, SMEM);

    cudaMemcpyAsync(hbuf, h, (size_t)BATCH * HID * sizeof(float), cudaMemcpyDeviceToDevice);

    const float dt = 1.0f / NSTEPS;

    // prep: fp16-round weights and h, compute all 40 c1 vectors
    {
        int n2;
        n2 = HID2 * HID / 2;   half2_kernel<<<(n2 + 255) / 256, 256>>>((const float2*)W1, (__half2*)w1, n2);
        n2 = HID2 * HID2 / 2;  half2_kernel<<<(n2 + 255) / 256, 256>>>((const float2*)W2, (__half2*)w2, n2);
        n2 = HID * HID2 / 2;   half2_kernel<<<(n2 + 255) / 256, 256>>>((const float2*)W3, (__half2*)w3, n2);
        n2 = BATCH * HID / 2;  half2_kernel<<<(n2 + 255) / 256, 256>>>((const float2*)h,  (__half2*)hr, n2);
        c1_all_kernel<<<NEVAL * HID2 / 8, 256>>>(W1, b1, Wt, bt, dt, c1);
    }

    dim3 blk(256);
    dim3 grd1(HID2 / 128, BATCH / 128);    // 8 x 64 = 512 CTAs
    dim3 grd3(HID  / 128, BATCH / 128);    // 4 x 64 = 256 CTAs

    for (int s = 0; s < NSTEPS; s++) {
        for (int st = 0; st < 4; st++) {
            const __half* Ain = (st == 0) ? hr : htmp;
            const float* c1e = c1 + (s * 4 + st) * HID2;
            launch_gemm(grd1, blk, SMEM, Ain, w1, c1e, x1, HID2, HID, -1, dt,
                        nullptr, nullptr, nullptr, nullptr);
            launch_gemm(grd1, blk, SMEM, x1, w2, b2, x2, HID2, HID2, -1, dt,
                        nullptr, nullptr, nullptr, nullptr);
            launch_gemm(grd3, blk, SMEM, x2, w3, b3, nullptr, HID, HID2, st, dt,
                        hbuf, accb, htmp, hr);
        }
    }

    cudaMemcpyAsync(d_out, hbuf, (size_t)BATCH * HID * sizeof(float), cudaMemcpyDeviceToDevice);
}

// round 12
// speedup vs baseline: 1.6080x; 1.0590x over previous
#include <cuda_runtime.h>
#include <cuda_fp16.h>
#include <cstdint>

#define BATCH 8192
#define HID   512
#define HID2  1024
#define NSTEPS 10
#define NEVAL  (NSTEPS*4)

// ---------------- scratch (device globals; no allocation anywhere) -----------
__device__ __half g_x1[(size_t)BATCH * HID2];    // tanh out, fp16
__device__ __half g_x2[(size_t)BATCH * HID2];
__device__ float  g_acc[(size_t)BATCH * HID];    // fp32 RK4 accumulator
__device__ __half g_htmp[(size_t)BATCH * HID];   // fp16 stage input
__device__ float  g_h[(size_t)BATCH * HID];      // fp32 state
__device__ __half g_hr[(size_t)BATCH * HID];     // fp16 copy of h
__device__ __half g_w1[(size_t)HID2 * HID];      // fp16 weights
__device__ __half g_w2[(size_t)HID2 * HID2];
__device__ __half g_w3[(size_t)HID  * HID2];
__device__ float  g_c1[NEVAL * HID2];            // fp32

// ---------------- helpers ----------------------------------------------------
__device__ __forceinline__ void mma16(float* d, const unsigned* a, const unsigned* b) {
    asm volatile(
        "mma.sync.aligned.m16n8k16.row.col.f32.f16.f16.f32 "
        "{%0,%1,%2,%3}, {%4,%5,%6,%7}, {%8,%9}, {%0,%1,%2,%3};\n"
        : "+f"(d[0]), "+f"(d[1]), "+f"(d[2]), "+f"(d[3])
        : "r"(a[0]), "r"(a[1]), "r"(a[2]), "r"(a[3]), "r"(b[0]), "r"(b[1]));
}

#define LDSM4(r, a) \
    asm volatile("ldmatrix.sync.aligned.m8n8.x4.shared.b16 {%0,%1,%2,%3}, [%4];" \
                 : "=r"((r)[0]), "=r"((r)[1]), "=r"((r)[2]), "=r"((r)[3]) : "r"(a))

// ---------------- prep kernels -----------------------------------------------
// fp32 -> fp16 (rne), 2 elems/thread
__global__ void half2_kernel(const float2* __restrict__ src, __half2* __restrict__ dst, int n2) {
    int i = blockIdx.x * blockDim.x + threadIdx.x;
    if (i < n2) {
        float2 v = src[i];
        dst[i] = __floats2half2_rn(v.x, v.y);
    }
}

// c1[e][j] = b1[j] + sum_i W1[j,i]*(t_e*Wt[i]+bt[i])   (fp32 inputs)
__global__ void c1_all_kernel(const float* __restrict__ W1, const float* __restrict__ b1,
                              const float* __restrict__ Wt, const float* __restrict__ bt,
                              float dt, float* __restrict__ out) {
    int gw = (blockIdx.x * blockDim.x + threadIdx.x) >> 5;
    int lane = threadIdx.x & 31;
    int e = gw >> 10;
    int j = gw & 1023;
    if (e >= NEVAL) return;
    int step = e >> 2, st = e & 3;
    float tv = step * dt + ((st == 0) ? 0.0f : (st == 3) ? dt : 0.5f * dt);
    const float* row = W1 + (size_t)j * HID;
    float s = 0.0f;
    #pragma unroll 4
    for (int i = lane; i < HID; i += 32)
        s = fmaf(row[i], fmaf(tv, Wt[i], bt[i]), s);
    #pragma unroll
    for (int o = 16; o; o >>= 1) s += __shfl_xor_sync(0xffffffffu, s, o);
    if (lane == 0) out[e * HID2 + j] = b1[j] + s;
}

// ---------------- GEMM: C = act( A[M,K] @ Bw[N,K]^T + bias[N] ) --------------
// fp16 operands, fp32 accumulate. CTA 128x128, 256 thr, 2(M)x4(N) warps,
// warp tile 64x32. Fragment loads via ldmatrix.x4 (12 LDSM + 32 HMMA per
// warp-chunk vs 48 LDS + 32 HMMA). 3-stage cp.async + PDL, occ 2.
// stage < 0 : tanh epilogue -> C (fp16). stage 0..3: fused RK4 (N == HID).
__global__ __launch_bounds__(256, 2)
void gemm_kernel(const __half* __restrict__ A, const __half* __restrict__ Bw,
                 const float* __restrict__ bias, __half* __restrict__ C,
                 int N, int K, int stage, float dt,
                 float* __restrict__ hbuf, float* __restrict__ accbuf,
                 __half* __restrict__ htmp, __half* __restrict__ hr) {
    extern __shared__ __half smem[];
    const int STG_B = 128 * 80;         // bytes per stage per matrix (row = 80 B)
    __half* As = smem;                  // 3 A stages
    __half* Bs = smem + 3 * (STG_B / 2);

    const int t = threadIdx.x;
    const int warp = t >> 5, lane = t & 31;
    const int wm = warp & 1, wn = warp >> 1;  // 2 x 4 warp grid, warp tile 64x32
    const int g = lane >> 2, q = lane & 3;
    const int bm = blockIdx.y * 128;
    const int bn = blockIdx.x * 128;

    // copy mapping: thread covers rows {t>>2, t>>2 + 64}, 16B segment (t&3)
    const int row0 = t >> 2;
    const int seg  = t & 3;

    const __half* Ag = A  + (size_t)(bm + row0) * K + seg * 8;
    const __half* Bg = Bw + (size_t)(bn + row0) * K + seg * 8;

    const unsigned smemA0 = (unsigned)__cvta_generic_to_shared(As);
    const unsigned smemB0 = (unsigned)__cvta_generic_to_shared(Bs);
    unsigned sA0 = smemA0 + row0 * 80 + seg * 16;
    unsigned sB0 = smemB0 + row0 * 80 + seg * 16;

    // ldmatrix lane addresses (stage-0 relative)
    // A x4 tile (16x16): lanes 0-15 -> rows 0-15 (k lo), 16-31 -> rows (k hi +16B)
    const unsigned aL0 = smemA0 + (unsigned)(wm * 64 + (lane & 15)) * 80
                       + ((lane >> 4) & 1) * 16;
    // B x4: m0/m1 = n rows g+0..7 (k lo/hi), m2/m3 = n rows +8 (k lo/hi)
    const unsigned bL0 = smemB0 + (unsigned)(wn * 32 + ((lane >> 4) & 1) * 8 + (lane & 7)) * 80
                       + ((lane >> 3) & 1) * 16;

    float acc[4][4][4];
    #pragma unroll
    for (int i = 0; i < 4; i++)
        #pragma unroll
        for (int j = 0; j < 4; j++)
            #pragma unroll
            for (int v = 0; v < 4; v++) acc[i][j][v] = 0.0f;

    const int KT = K >> 5;

    #define LOAD_A(kt, s)                                                              \
    {                                                                                  \
        const __half* ap = Ag + (kt) * 32;                                             \
        unsigned sa = sA0 + (unsigned)(s) * STG_B;                                     \
        _Pragma("unroll")                                                              \
        for (int i = 0; i < 2; i++)                                                    \
            asm volatile("cp.async.cg.shared.global [%0], [%1], 16;\n"                 \
                         :: "r"(sa + i * 64 * 80), "l"(ap + (size_t)i * 64 * K));      \
    }
    #define LOAD_B(kt, s)                                                              \
    {                                                                                  \
        const __half* bp = Bg + (kt) * 32;                                             \
        unsigned sb = sB0 + (unsigned)(s) * STG_B;                                     \
        _Pragma("unroll")                                                              \
        for (int i = 0; i < 2; i++)                                                    \
            asm volatile("cp.async.cg.shared.global [%0], [%1], 16;\n"                 \
                         :: "r"(sb + i * 64 * 80), "l"(bp + (size_t)i * 64 * K));      \
    }
    #define COMMIT() asm volatile("cp.async.commit_group;\n")

    // --- prologue: weights first (independent of predecessor), then gate on A ---
    LOAD_B(0, 0);
    LOAD_B(1, 1);
    COMMIT();                                       // group: B0+B1
    asm volatile("griddepcontrol.wait;" ::: "memory");
    LOAD_A(0, 0);
    COMMIT();                                       // group: A0
    LOAD_A(1, 1);
    COMMIT();                                       // group: A1
    asm volatile("griddepcontrol.launch_dependents;" ::: "memory");

    for (int kt = 0; kt < KT; kt++) {
        asm volatile("cp.async.wait_group 1;\n");
        __syncthreads();
        const int cur = kt % 3;
        const unsigned aS = aL0 + (unsigned)cur * STG_B;
        const unsigned bS = bL0 + (unsigned)cur * STG_B;
        #pragma unroll
        for (int s = 0; s < 2; s++) {              // two k16 steps per 32-chunk
            unsigned bfr[8];                        // [fn][2] for fn 0..3
            LDSM4(&bfr[0], bS + s * 32);            // fn0, fn1
            LDSM4(&bfr[4], bS + s * 32 + 16 * 80);  // fn2, fn3
            #pragma unroll
            for (int fm = 0; fm < 4; fm++) {
                unsigned af[4];
                LDSM4(af, aS + s * 32 + (unsigned)(fm * 16) * 80);
                #pragma unroll
                for (int fn = 0; fn < 4; fn++)
                    mma16(acc[fm][fn], af, &bfr[fn * 2]);
            }
        }
        if (kt + 2 < KT) {
            const int nxt = (kt + 2) % 3;
            LOAD_A(kt + 2, nxt);
            LOAD_B(kt + 2, nxt);
            COMMIT();
        }
    }
    #undef LOAD_A
    #undef LOAD_B
    #undef COMMIT

    // ---------------- epilogue ----------------
    #pragma unroll
    for (int fm = 0; fm < 4; fm++) {
        int r0 = bm + wm * 64 + fm * 16 + g;
        int r1 = r0 + 8;
        #pragma unroll
        for (int fn = 0; fn < 4; fn++) {
            int c = bn + wn * 32 + fn * 8 + 2 * q;
            float bc0 = bias[c], bc1 = bias[c + 1];
            float v[4];
            v[0] = acc[fm][fn][0] + bc0;
            v[1] = acc[fm][fn][1] + bc1;
            v[2] = acc[fm][fn][2] + bc0;
            v[3] = acc[fm][fn][3] + bc1;
            int idx[4] = { r0 * N + c, r0 * N + c + 1, r1 * N + c, r1 * N + c + 1 };
            if (stage < 0) {
                #pragma unroll
                for (int u = 0; u < 4; u++)
                    C[idx[u]] = __float2half_rn(tanhf(v[u]));
            } else if (stage == 0) {
                #pragma unroll
                for (int u = 0; u < 4; u++) {
                    accbuf[idx[u]] = v[u];
                    htmp[idx[u]]   = __float2half_rn(hbuf[idx[u]] + 0.5f * dt * v[u]);
                }
            } else if (stage == 1) {
                #pragma unroll
                for (int u = 0; u < 4; u++) {
                    accbuf[idx[u]] += 2.0f * v[u];
                    htmp[idx[u]]    = __float2half_rn(hbuf[idx[u]] + 0.5f * dt * v[u]);
                }
            } else if (stage == 2) {
                #pragma unroll
                for (int u = 0; u < 4; u++) {
                    accbuf[idx[u]] += 2.0f * v[u];
                    htmp[idx[u]]    = __float2half_rn(hbuf[idx[u]] + dt * v[u]);
                }
            } else {
                #pragma unroll
                for (int u = 0; u < 4; u++) {
                    float hn = hbuf[idx[u]] + (dt / 6.0f) * (accbuf[idx[u]] + v[u]);
                    hbuf[idx[u]] = hn;
                    hr[idx[u]]   = __float2half_rn(hn);
                }
            }
        }
    }
}

// ---------------- launch -----------------------------------------------------
static void launch_gemm(dim3 grd, dim3 blk, int smem,
                        const __half* A, const __half* Bw, const float* bias, __half* C,
                        int N, int K, int stage, float dt,
                        float* hbuf, float* accbuf, __half* htmp, __half* hr) {
    cudaLaunchConfig_t cfg = {};
    cfg.gridDim = grd;
    cfg.blockDim = blk;
    cfg.dynamicSmemBytes = (size_t)smem;
    cfg.stream = 0;
    cudaLaunchAttribute at[1];
    at[0].id = cudaLaunchAttributeProgrammaticStreamSerialization;
    at[0].val.programmaticStreamSerializationAllowed = 1;
    cfg.attrs = at;
    cfg.numAttrs = 1;
    cudaLaunchKernelEx(&cfg, gemm_kernel, A, Bw, bias, C, N, K, stage, dt,
                       hbuf, accbuf, htmp, hr);
}

extern "C" void kernel_launch(void* const* d_in, const int* in_sizes, int n_in,
                              void* d_out, int out_size) {
    const float* h  = (const float*)d_in[0];
    const float* W1 = (const float*)d_in[1];
    const float* b1 = (const float*)d_in[2];
    const float* W2 = (const float*)d_in[3];
    const float* b2 = (const float*)d_in[4];
    const float* W3 = (const float*)d_in[5];
    const float* b3 = (const float*)d_in[6];
    const float* Wt = (const float*)d_in[7];
    const float* bt = (const float*)d_in[8];
    (void)in_sizes; (void)n_in; (void)out_size;

    __half *x1, *x2, *htmp, *hr, *w1, *w2, *w3;
    float *accb, *hbuf, *c1;
    cudaGetSymbolAddress((void**)&x1,   g_x1);
    cudaGetSymbolAddress((void**)&x2,   g_x2);
    cudaGetSymbolAddress((void**)&accb, g_acc);
    cudaGetSymbolAddress((void**)&htmp, g_htmp);
    cudaGetSymbolAddress((void**)&hbuf, g_h);
    cudaGetSymbolAddress((void**)&hr,   g_hr);
    cudaGetSymbolAddress((void**)&w1,   g_w1);
    cudaGetSymbolAddress((void**)&w2,   g_w2);
    cudaGetSymbolAddress((void**)&w3,   g_w3);
    cudaGetSymbolAddress((void**)&c1,   g_c1);

    const int SMEM = 6 * 128 * 80;      // 61440 B (3 stages x (A+B))
    cudaFuncSetAttribute(gemm_kernel, cudaFuncAttributeMaxDynamicSharedMemorySize, SMEM);

    cudaMemcpyAsync(hbuf, h, (size_t)BATCH * HID * sizeof(float), cudaMemcpyDeviceToDevice);

    const float dt = 1.0f / NSTEPS;

    // prep: fp16-round weights and h, compute all 40 c1 vectors
    {
        int n2;
        n2 = HID2 * HID / 2;   half2_kernel<<<(n2 + 255) / 256, 256>>>((const float2*)W1, (__half2*)w1, n2);
        n2 = HID2 * HID2 / 2;  half2_kernel<<<(n2 + 255) / 256, 256>>>((const float2*)W2, (__half2*)w2, n2);
        n2 = HID * HID2 / 2;   half2_kernel<<<(n2 + 255) / 256, 256>>>((const float2*)W3, (__half2*)w3, n2);
        n2 = BATCH * HID / 2;  half2_kernel<<<(n2 + 255) / 256, 256>>>((const float2*)h,  (__half2*)hr, n2);
        c1_all_kernel<<<NEVAL * HID2 / 8, 256>>>(W1, b1, Wt, bt, dt, c1);
    }

    dim3 blk(256);
    dim3 grd1(HID2 / 128, BATCH / 128);    // 8 x 64 = 512 CTAs
    dim3 grd3(HID  / 128, BATCH / 128);    // 4 x 64 = 256 CTAs

    for (int s = 0; s < NSTEPS; s++) {
        for (int st = 0; st < 4; st++) {
            const __half* Ain = (st == 0) ? hr : htmp;
            const float* c1e = c1 + (s * 4 + st) * HID2;
            launch_gemm(grd1, blk, SMEM, Ain, w1, c1e, x1, HID2, HID, -1, dt,
                        nullptr, nullptr, nullptr, nullptr);
            launch_gemm(grd1, blk, SMEM, x1, w2, b2, x2, HID2, HID2, -1, dt,
                        nullptr, nullptr, nullptr, nullptr);
            launch_gemm(grd3, blk, SMEM, x2, w3, b3, nullptr, HID, HID2, st, dt,
                        hbuf, accb, htmp, hr);
        }
    }

    cudaMemcpyAsync(d_out, hbuf, (size_t)BATCH * HID * sizeof(float), cudaMemcpyDeviceToDevice);
}

// round 13
// speedup vs baseline: 1.9691x; 1.2245x over previous
#include <cuda_runtime.h>
#include <cuda_fp16.h>
#include <cstdint>

#define BATCH 8192
#define HID   512
#define HID2  1024
#define NSTEPS 10
#define NEVAL  (NSTEPS*4)
#define ITEMS_PER_EVAL 1280          // 512 G1 + 512 G2 + 256 G3
#define TOTAL_ITEMS (NEVAL*ITEMS_PER_EVAL)
#define NSYNC (NEVAL*3*64 + 1)       // counters + ticket

// ---------------- scratch (device globals; no allocation anywhere) -----------
__device__ __half g_x1[(size_t)BATCH * HID2];
__device__ __half g_x2[(size_t)BATCH * HID2];
__device__ float  g_acc[(size_t)BATCH * HID];
__device__ __half g_htmp[(size_t)BATCH * HID];
__device__ float  g_h[(size_t)BATCH * HID];
__device__ __half g_hr[(size_t)BATCH * HID];
__device__ __half g_w1[(size_t)HID2 * HID];
__device__ __half g_w2[(size_t)HID2 * HID2];
__device__ __half g_w3[(size_t)HID  * HID2];
__device__ float  g_c1[NEVAL * HID2];
__device__ int    g_sync[NSYNC];

// ---------------- helpers ----------------------------------------------------
__device__ __forceinline__ void mma16(float* d, const unsigned* a, const unsigned* b) {
    asm volatile(
        "mma.sync.aligned.m16n8k16.row.col.f32.f16.f16.f32 "
        "{%0,%1,%2,%3}, {%4,%5,%6,%7}, {%8,%9}, {%0,%1,%2,%3};\n"
        : "+f"(d[0]), "+f"(d[1]), "+f"(d[2]), "+f"(d[3])
        : "r"(a[0]), "r"(a[1]), "r"(a[2]), "r"(a[3]), "r"(b[0]), "r"(b[1]));
}

#define LDSM4(r, a) \
    asm volatile("ldmatrix.sync.aligned.m8n8.x4.shared.b16 {%0,%1,%2,%3}, [%4];" \
                 : "=r"((r)[0]), "=r"((r)[1]), "=r"((r)[2]), "=r"((r)[3]) : "r"(a))

// ---------------- prep kernels -----------------------------------------------
__global__ void half2_kernel(const float2* __restrict__ src, __half2* __restrict__ dst, int n2) {
    int i = blockIdx.x * blockDim.x + threadIdx.x;
    if (i < n2) {
        float2 v = src[i];
        dst[i] = __floats2half2_rn(v.x, v.y);
    }
}

__global__ void zero_sync_kernel(int* p, int n) {
    int i = blockIdx.x * blockDim.x + threadIdx.x;
    if (i < n) p[i] = 0;
}

// c1[e][j] = b1[j] + sum_i W1[j,i]*(t_e*Wt[i]+bt[i])
__global__ void c1_all_kernel(const float* __restrict__ W1, const float* __restrict__ b1,
                              const float* __restrict__ Wt, const float* __restrict__ bt,
                              float dt, float* __restrict__ out) {
    int gw = (blockIdx.x * blockDim.x + threadIdx.x) >> 5;
    int lane = threadIdx.x & 31;
    int e = gw >> 10;
    int j = gw & 1023;
    if (e >= NEVAL) return;
    int step = e >> 2, st = e & 3;
    float tv = step * dt + ((st == 0) ? 0.0f : (st == 3) ? dt : 0.5f * dt);
    const float* row = W1 + (size_t)j * HID;
    float s = 0.0f;
    #pragma unroll 4
    for (int i = lane; i < HID; i += 32)
        s = fmaf(row[i], fmaf(tv, Wt[i], bt[i]), s);
    #pragma unroll
    for (int o = 16; o; o >>= 1) s += __shfl_xor_sync(0xffffffffu, s, o);
    if (lane == 0) out[e * HID2 + j] = b1[j] + s;
}

// ---------------- persistent dataflow kernel ---------------------------------
// One launch runs all 40 evals x 3 GEMMs as 51200 tile-items pulled from a
// global ticket, with per-(eval,128-rowblock) dependency counters.
// Tile body = proven R12 ldmatrix fp16 kernel (CTA 128x128, 2x4 warps).
__global__ __launch_bounds__(256, 2)
void ode_persistent(__half* x1, __half* x2, __half* htmp, __half* hr,
                    const __half* w1, const __half* w2, const __half* w3,
                    const float* c1, const float* b2, const float* b3,
                    float* hbuf, float* accbuf, int* syncbuf, float dt) {
    extern __shared__ __half smem[];
    const int STG_B = 128 * 80;               // bytes per stage per matrix
    __half* As = smem;
    __half* Bs = smem + 3 * (STG_B / 2);
    __shared__ int s_item;

    const int t = threadIdx.x;
    const int warp = t >> 5, lane = t & 31;
    const int wm = warp & 1, wn = warp >> 1;  // 2 x 4 warp grid, warp tile 64x32
    const int g = lane >> 2, q = lane & 3;
    const int row0 = t >> 2;
    const int seg  = t & 3;

    const unsigned smemA0 = (unsigned)__cvta_generic_to_shared(As);
    const unsigned smemB0 = (unsigned)__cvta_generic_to_shared(Bs);
    const unsigned sA0 = smemA0 + row0 * 80 + seg * 16;
    const unsigned sB0 = smemB0 + row0 * 80 + seg * 16;
    const unsigned aL0 = smemA0 + (unsigned)(wm * 64 + (lane & 15)) * 80
                       + ((lane >> 4) & 1) * 16;
    const unsigned bL0 = smemB0 + (unsigned)(wn * 32 + ((lane >> 4) & 1) * 8 + (lane & 7)) * 80
                       + ((lane >> 3) & 1) * 16;
    int* ticket = syncbuf + NEVAL * 3 * 64;

    for (;;) {
        if (t == 0) s_item = atomicAdd(ticket, 1);
        __syncthreads();
        const int item = s_item;
        if (item >= TOTAL_ITEMS) break;

        const int e  = item / ITEMS_PER_EVAL;
        const int r  = item - e * ITEMS_PER_EVAL;
        const int st = e & 3;

        const __half *A, *Bw;
        const float* bias;
        __half* C;
        int N, K, bm, bn, stage, depneed = 0;
        const int* dep = nullptr;
        int* sig;
        if (r < 512) {                       // GEMM1
            bm = r >> 3; bn = r & 7;
            A = (st == 0) ? hr : htmp; Bw = w1; bias = c1 + e * HID2; C = x1;
            N = HID2; K = HID; stage = -1;
            if (e > 0) { dep = syncbuf + ((e - 1) * 3 + 2) * 64 + bm; depneed = 4; }
            sig = syncbuf + (e * 3 + 0) * 64 + bm;
        } else if (r < 1024) {               // GEMM2
            int r2 = r - 512; bm = r2 >> 3; bn = r2 & 7;
            A = x1; Bw = w2; bias = b2; C = x2;
            N = HID2; K = HID2; stage = -1;
            dep = syncbuf + (e * 3 + 0) * 64 + bm; depneed = 8;
            sig = syncbuf + (e * 3 + 1) * 64 + bm;
        } else {                             // GEMM3 (+ fused RK4 epilogue)
            int r3 = r - 1024; bm = r3 >> 2; bn = r3 & 3;
            A = x2; Bw = w3; bias = b3; C = nullptr;
            N = HID; K = HID2; stage = st;
            dep = syncbuf + (e * 3 + 1) * 64 + bm; depneed = 8;
            sig = syncbuf + (e * 3 + 2) * 64 + bm;
        }
        const int bmo = bm << 7, bno = bn << 7;
        const __half* Bg = Bw + (size_t)(bno + row0) * K + seg * 8;

        #define LOAD_A(kt, s)                                                          \
        {                                                                              \
            const __half* ap = Ag + (kt) * 32;                                         \
            unsigned sa = sA0 + (unsigned)(s) * STG_B;                                 \
            _Pragma("unroll")                                                          \
            for (int i = 0; i < 2; i++)                                                \
                asm volatile("cp.async.cg.shared.global [%0], [%1], 16;\n"             \
                             :: "r"(sa + i * 64 * 80), "l"(ap + (size_t)i * 64 * K));  \
        }
        #define LOAD_B(kt, s)                                                          \
        {                                                                              \
            const __half* bp = Bg + (kt) * 32;                                         \
            unsigned sb = sB0 + (unsigned)(s) * STG_B;                                 \
            _Pragma("unroll")                                                          \
            for (int i = 0; i < 2; i++)                                                \
                asm volatile("cp.async.cg.shared.global [%0], [%1], 16;\n"             \
                             :: "r"(sb + i * 64 * 80), "l"(bp + (size_t)i * 64 * K));  \
        }
        #define COMMIT() asm volatile("cp.async.commit_group;\n")

        // weights first (dep-free), then spin on producer counters, then A
        LOAD_B(0, 0);
        LOAD_B(1, 1);
        COMMIT();
        if (t == 0 && depneed) {
            while (*(volatile const int*)dep < depneed) __nanosleep(200);
            __threadfence();
        }
        __syncthreads();
        const __half* Ag = A + (size_t)(bmo + row0) * K + seg * 8;
        LOAD_A(0, 0);
        COMMIT();
        LOAD_A(1, 1);
        COMMIT();

        float acc[4][4][4];
        #pragma unroll
        for (int i = 0; i < 4; i++)
            #pragma unroll
            for (int j = 0; j < 4; j++)
                #pragma unroll
                for (int v = 0; v < 4; v++) acc[i][j][v] = 0.0f;

        const int KT = K >> 5;
        for (int kt = 0; kt < KT; kt++) {
            if (kt + 1 == KT) asm volatile("cp.async.wait_group 0;\n");
            else              asm volatile("cp.async.wait_group 1;\n");
            __syncthreads();
            const int cur = kt % 3;
            const unsigned aS = aL0 + (unsigned)cur * STG_B;
            const unsigned bS = bL0 + (unsigned)cur * STG_B;
            #pragma unroll
            for (int s = 0; s < 2; s++) {
                unsigned bfr[8];
                LDSM4(&bfr[0], bS + s * 32);
                LDSM4(&bfr[4], bS + s * 32 + 16 * 80);
                #pragma unroll
                for (int fm = 0; fm < 4; fm++) {
                    unsigned af[4];
                    LDSM4(af, aS + s * 32 + (unsigned)(fm * 16) * 80);
                    #pragma unroll
                    for (int fn = 0; fn < 4; fn++)
                        mma16(acc[fm][fn], af, &bfr[fn * 2]);
                }
            }
            if (kt + 2 < KT) {
                const int nxt = (kt + 2) % 3;
                LOAD_A(kt + 2, nxt);
                LOAD_B(kt + 2, nxt);
                COMMIT();
            }
        }
        #undef LOAD_A
        #undef LOAD_B
        #undef COMMIT

        // epilogue
        #pragma unroll
        for (int fm = 0; fm < 4; fm++) {
            int r0 = bmo + wm * 64 + fm * 16 + g;
            int r1 = r0 + 8;
            #pragma unroll
            for (int fn = 0; fn < 4; fn++) {
                int c = bno + wn * 32 + fn * 8 + 2 * q;
                float bc0 = bias[c], bc1 = bias[c + 1];
                float v[4];
                v[0] = acc[fm][fn][0] + bc0;
                v[1] = acc[fm][fn][1] + bc1;
                v[2] = acc[fm][fn][2] + bc0;
                v[3] = acc[fm][fn][3] + bc1;
                int idx[4] = { r0 * N + c, r0 * N + c + 1, r1 * N + c, r1 * N + c + 1 };
                if (stage < 0) {
                    #pragma unroll
                    for (int u = 0; u < 4; u++)
                        C[idx[u]] = __float2half_rn(tanhf(v[u]));
                } else if (stage == 0) {
                    #pragma unroll
                    for (int u = 0; u < 4; u++) {
                        accbuf[idx[u]] = v[u];
                        htmp[idx[u]]   = __float2half_rn(hbuf[idx[u]] + 0.5f * dt * v[u]);
                    }
                } else if (stage == 1) {
                    #pragma unroll
                    for (int u = 0; u < 4; u++) {
                        accbuf[idx[u]] += 2.0f * v[u];
                        htmp[idx[u]]    = __float2half_rn(hbuf[idx[u]] + 0.5f * dt * v[u]);
                    }
                } else if (stage == 2) {
                    #pragma unroll
                    for (int u = 0; u < 4; u++) {
                        accbuf[idx[u]] += 2.0f * v[u];
                        htmp[idx[u]]    = __float2half_rn(hbuf[idx[u]] + dt * v[u]);
                    }
                } else {
                    #pragma unroll
                    for (int u = 0; u < 4; u++) {
                        float hn = hbuf[idx[u]] + (dt / 6.0f) * (accbuf[idx[u]] + v[u]);
                        hbuf[idx[u]] = hn;
                        hr[idx[u]]   = __float2half_rn(hn);
                    }
                }
            }
        }

        __threadfence();
        __syncthreads();
        if (t == 0) atomicAdd(sig, 1);
    }
}

// ---------------- launch -----------------------------------------------------
extern "C" void kernel_launch(void* const* d_in, const int* in_sizes, int n_in,
                              void* d_out, int out_size) {
    const float* h  = (const float*)d_in[0];
    const float* W1 = (const float*)d_in[1];
    const float* b1 = (const float*)d_in[2];
    const float* W2 = (const float*)d_in[3];
    const float* b2 = (const float*)d_in[4];
    const float* W3 = (const float*)d_in[5];
    const float* b3 = (const float*)d_in[6];
    const float* Wt = (const float*)d_in[7];
    const float* bt = (const float*)d_in[8];
    (void)in_sizes; (void)n_in; (void)out_size;

    __half *x1, *x2, *htmp, *hr, *w1, *w2, *w3;
    float *accb, *hbuf, *c1;
    int* syncbuf;
    cudaGetSymbolAddress((void**)&x1,      g_x1);
    cudaGetSymbolAddress((void**)&x2,      g_x2);
    cudaGetSymbolAddress((void**)&accb,    g_acc);
    cudaGetSymbolAddress((void**)&htmp,    g_htmp);
    cudaGetSymbolAddress((void**)&hbuf,    g_h);
    cudaGetSymbolAddress((void**)&hr,      g_hr);
    cudaGetSymbolAddress((void**)&w1,      g_w1);
    cudaGetSymbolAddress((void**)&w2,      g_w2);
    cudaGetSymbolAddress((void**)&w3,      g_w3);
    cudaGetSymbolAddress((void**)&c1,      g_c1);
    cudaGetSymbolAddress((void**)&syncbuf, g_sync);

    const int SMEM = 6 * 128 * 80;      // 61440 B (3 stages x (A+B))
    cudaFuncSetAttribute(ode_persistent, cudaFuncAttributeMaxDynamicSharedMemorySize, SMEM);

    cudaMemcpyAsync(hbuf, h, (size_t)BATCH * HID * sizeof(float), cudaMemcpyDeviceToDevice);

    const float dt = 1.0f / NSTEPS;

    // prep: fp16-round weights and h, c1 vectors, zero sync counters
    {
        int n2;
        n2 = HID2 * HID / 2;   half2_kernel<<<(n2 + 255) / 256, 256>>>((const float2*)W1, (__half2*)w1, n2);
        n2 = HID2 * HID2 / 2;  half2_kernel<<<(n2 + 255) / 256, 256>>>((const float2*)W2, (__half2*)w2, n2);
        n2 = HID * HID2 / 2;   half2_kernel<<<(n2 + 255) / 256, 256>>>((const float2*)W3, (__half2*)w3, n2);
        n2 = BATCH * HID / 2;  half2_kernel<<<(n2 + 255) / 256, 256>>>((const float2*)h,  (__half2*)hr, n2);
        c1_all_kernel<<<NEVAL * HID2 / 8, 256>>>(W1, b1, Wt, bt, dt, c1);
        zero_sync_kernel<<<(NSYNC + 255) / 256, 256>>>(syncbuf, NSYNC);
    }

    // one persistent kernel runs the whole 40-eval chain
    ode_persistent<<<296, 256, SMEM>>>(x1, x2, htmp, hr, w1, w2, w3,
                                       c1, b2, b3, hbuf, accb, syncbuf, dt);

    cudaMemcpyAsync(d_out, hbuf, (size_t)BATCH * HID * sizeof(float), cudaMemcpyDeviceToDevice);
}